// round 5
// baseline (speedup 1.0000x reference)
#include <cuda_runtime.h>
#include <cuda_bf16.h>

// Problem constants
#define N_  128
#define D_  512
#define IC_ 32
#define OC_ 8
#define R_  4
#define W_ELEMS_ (D_ * IC_ * OC_ * R_)          // 524288
#define OUT_HALF_ ((size_t)N_ * D_ * OC_ * R_)  // 2097152

#define CH_    4                  // ics per pipeline chunk
#define NCH_   (IC_ / CH_)        // 8 chunks
#define NSLOT_ 3                  // smem slots (prefetch distance 2)
#define NROWS_ 64                 // n-rows per block
#define SROW4_ 20                 // smem words per row per chunk (16 data + 4 pad)
#define SROWO_ 36                 // smem words per row for output staging (32 + 4 pad)

// ---- packed fp32x2 helpers ----
__device__ __forceinline__ unsigned long long pk2(float a, float b) {
    unsigned long long r;
    asm("mov.b64 %0, {%1, %2};" : "=l"(r) : "f"(a), "f"(b));
    return r;
}
__device__ __forceinline__ float2 upk2(unsigned long long a) {
    float lo, hi;
    asm("mov.b64 {%0, %1}, %2;" : "=f"(lo), "=f"(hi) : "l"(a));
    return make_float2(lo, hi);
}
__device__ __forceinline__ void fma2(unsigned long long& d,
                                     unsigned long long a, unsigned long long b) {
    asm("fma.rn.f32x2 %0, %1, %2, %0;" : "+l"(d) : "l"(a), "l"(b));
}
__device__ __forceinline__ unsigned long long mul2(unsigned long long a,
                                                   unsigned long long b) {
    unsigned long long r;
    asm("mul.rn.f32x2 %0, %1, %2;" : "=l"(r) : "l"(a), "l"(b));
    return r;
}

// Block: 128 threads = one d, 64 n-rows x 2 oc-groups. Grid = 1024.
// 5 blocks/SM (regs<=102 via launch_bounds, smem ~35KB).
__global__ __launch_bounds__(128, 5)
void logmix_kernel(const float4* __restrict__ x4,
                   const float4* __restrict__ v4,
                   const float*  __restrict__ w,
                   float* __restrict__ out)
{
    __shared__ float xs[NSLOT_ * NROWS_ * SROW4_];   // 15 KB: x chunk slots / P out
    __shared__ float vs[NSLOT_ * NROWS_ * SROW4_];   // 15 KB: v chunk slots / V out
    __shared__ ulonglong2 wpk[IC_ * OC_];            //  4 KB: softmax(w) packed f32x2

    const int t = threadIdx.x;
    const int d = blockIdx.x >> 1;
    const int h = blockIdx.x & 1;          // n-half: rows h*64 .. h*64+63

    // loader role: thread t loads float4-slot fi of rows r0, r0+32
    const int fi = t & 3;
    const int r0 = t >> 2;                 // 0..31
    const unsigned xs0 = (unsigned)__cvta_generic_to_shared(xs);
    const unsigned vs0 = (unsigned)__cvta_generic_to_shared(vs);
    const unsigned slotstride = NROWS_ * SROW4_ * 4;  // bytes per slot

    // ---- prologue: issue chunks 0 and 1 ----
    #pragma unroll
    for (int p = 0; p < 2; ++p) {
        const unsigned xb = xs0 + p * slotstride;
        const unsigned vb = vs0 + p * slotstride;
        #pragma unroll
        for (int j = 0; j < 2; ++j) {
            const int row = r0 + j * 32;
            const int n   = h * NROWS_ + row;
            const size_t g = ((size_t)n * D_ + d) * 32 + (size_t)(p * CH_ + fi);
            const unsigned so = (unsigned)((row * SROW4_ + fi * 4) * 4);
            asm volatile("cp.async.cg.shared.global [%0], [%1], 16;"
                         :: "r"(xb + so), "l"(x4 + g));
            asm volatile("cp.async.cg.shared.global [%0], [%1], 16;"
                         :: "r"(vb + so), "l"(v4 + g));
        }
        asm volatile("cp.async.commit_group;");
    }

    // ---- Stage raw weights (coalesced), softmax over ic in smem ----
    float* wf = reinterpret_cast<float*>(wpk);
    const float* wd = w + (size_t)d * (IC_ * OC_ * R_);
    #pragma unroll
    for (int i = 0; i < 8; ++i)
        wf[t + i * 128] = wd[t + i * 128];
    __syncthreads();

    if (t < 32) {                  // one thread per (oc,r) column; bank t -> conflict-free
        float s = 0.0f;
        #pragma unroll
        for (int ic = 0; ic < IC_; ++ic) {
            float e = __expf(wf[ic * 32 + t]);
            wf[ic * 32 + t] = e;
            s += e;
        }
        const float inv = 1.0f / s;
        #pragma unroll
        for (int ic = 0; ic < IC_; ++ic)
            wf[ic * 32 + t] *= inv;
    }
    // (softmax writes ordered before wpk reads by the per-chunk barrier below)

    // compute role: thread t handles row (t>>1), oc-group (t&1)*4
    const int crow = t >> 1;
    const int ocb  = (t & 1) * 4;

    unsigned long long aP[4][2], aV[4][2];
    #pragma unroll
    for (int oc = 0; oc < 4; ++oc) {
        aP[oc][0] = aP[oc][1] = 0ull;
        aV[oc][0] = aV[oc][1] = 0ull;
    }

    // ---- Pipelined main loop: distance-2 prefetch over 3 slots ----
    #pragma unroll 1
    for (int s = 0; s < NCH_; ++s) {
        if (s + 2 < NCH_) {
            const int slot = (s + 2) % NSLOT_;
            const unsigned xb = xs0 + slot * slotstride;
            const unsigned vb = vs0 + slot * slotstride;
            #pragma unroll
            for (int j = 0; j < 2; ++j) {
                const int row = r0 + j * 32;
                const int n   = h * NROWS_ + row;
                const size_t g = ((size_t)n * D_ + d) * 32 + (size_t)((s + 2) * CH_ + fi);
                const unsigned so = (unsigned)((row * SROW4_ + fi * 4) * 4);
                asm volatile("cp.async.cg.shared.global [%0], [%1], 16;"
                             :: "r"(xb + so), "l"(x4 + g));
                asm volatile("cp.async.cg.shared.global [%0], [%1], 16;"
                             :: "r"(vb + so), "l"(v4 + g));
            }
            asm volatile("cp.async.commit_group;");
            asm volatile("cp.async.wait_group 2;" ::: "memory");
        } else if (s + 2 == NCH_) {
            asm volatile("cp.async.wait_group 1;" ::: "memory");
        } else {
            asm volatile("cp.async.wait_group 0;" ::: "memory");
        }
        __syncthreads();   // chunk s fully visible to all threads

        const int slot = s % NSLOT_;
        const float4* xrow = reinterpret_cast<const float4*>(&xs[slot * NROWS_ * SROW4_ + crow * SROW4_]);
        const float4* vrow = reinterpret_cast<const float4*>(&vs[slot * NROWS_ * SROW4_ + crow * SROW4_]);
        #pragma unroll
        for (int ic = 0; ic < CH_; ++ic) {
            const float4 xv = xrow[ic];
            const float4 vv = vrow[ic];
            const float e0 = __expf(xv.x), e1 = __expf(xv.y);
            const float e2 = __expf(xv.z), e3 = __expf(xv.w);
            // t_r = exp(vars_r) + E_r^2  (left+right logsumexp fused into one sum)
            const float t0 = fmaf(e0, e0, __expf(vv.x));
            const float t1 = fmaf(e1, e1, __expf(vv.y));
            const float t2 = fmaf(e2, e2, __expf(vv.z));
            const float t3 = fmaf(e3, e3, __expf(vv.w));
            const unsigned long long e01 = pk2(e0, e1), e23 = pk2(e2, e3);
            const unsigned long long t01 = pk2(t0, t1), t23 = pk2(t2, t3);
            const int icg = s * CH_ + ic;
            #pragma unroll
            for (int oc = 0; oc < 4; ++oc) {
                const ulonglong2 wu = wpk[icg * OC_ + ocb + oc];  // 2-addr LDS.128
                fma2(aP[oc][0], wu.x, e01);
                fma2(aP[oc][1], wu.y, e23);
                fma2(aV[oc][0], mul2(wu.x, wu.x), t01);           // w^2 in registers
                fma2(aV[oc][1], mul2(wu.y, wu.y), t23);
            }
        }
        __syncthreads();   // all reads of slot s done before iter s+1 refills it
    }

    // ---- Epilogue: logs into reused smem (stride 36), own row/oc-group ----
    #pragma unroll
    for (int oc = 0; oc < 4; ++oc) {
        const float2 p0 = upk2(aP[oc][0]), p1 = upk2(aP[oc][1]);
        const float2 q0 = upk2(aV[oc][0]), q1 = upk2(aV[oc][1]);
        reinterpret_cast<float4*>(&xs[crow * SROWO_])[ocb + oc] =
            make_float4(__logf(p0.x), __logf(p0.y), __logf(p1.x), __logf(p1.y));
        reinterpret_cast<float4*>(&vs[crow * SROWO_])[ocb + oc] =
            make_float4(__logf(q0.x), __logf(q0.y), __logf(q1.x), __logf(q1.y));
    }
    __syncthreads();

    // ---- Cooperative coalesced stores: 4 full 128B rows per warp instr ----
    const int fo = t & 7;
    const int ro = t >> 3;                 // 0..15
    float4* outP = reinterpret_cast<float4*>(out);
    float4* outV = reinterpret_cast<float4*>(out + OUT_HALF_);
    #pragma unroll
    for (int j = 0; j < 4; ++j) {
        const int row = ro + j * 16;
        const int n   = h * NROWS_ + row;
        const size_t g = ((size_t)n * D_ + d) * 8 + fo;
        outP[g] = reinterpret_cast<const float4*>(&xs[row * SROWO_])[fo];
        outV[g] = reinterpret_cast<const float4*>(&vs[row * SROWO_])[fo];
    }
}

extern "C" void kernel_launch(void* const* d_in, const int* in_sizes, int n_in,
                              void* d_out, int out_size)
{
    // Expected order: x, vars, weights. Defensive: weights is the W_ELEMS_ one.
    const float* x = (const float*)d_in[0];
    const float* v = (const float*)d_in[1];
    const float* w = (const float*)d_in[2];
    if (n_in >= 3 && in_sizes[2] != W_ELEMS_) {
        int wi = -1;
        for (int i = 0; i < 3; ++i) if (in_sizes[i] == W_ELEMS_) { wi = i; break; }
        if (wi == 0)      { w = (const float*)d_in[0]; x = (const float*)d_in[1]; v = (const float*)d_in[2]; }
        else if (wi == 1) { x = (const float*)d_in[0]; w = (const float*)d_in[1]; v = (const float*)d_in[2]; }
    }

    logmix_kernel<<<D_ * 2, 128>>>((const float4*)x, (const float4*)v, w, (float*)d_out);
}